// round 11
// baseline (speedup 1.0000x reference)
#include <cuda_runtime.h>
#include <cuda_bf16.h>
#include <cuda_fp16.h>
#include <math.h>
#include <stdint.h>

#define NPTS 262144
#define CCH  256
#define KCLS 20
#define BN_TOT 288            // 256 h cols + 32 padded logit cols
#define NB_COLS 96            // N columns per CTA (3 N-tiles)

// ---------------- device globals ----------------
__device__ __half g_Bh[BN_TOT * CCH];              // B^T fp16 [n][k]
__device__ __half g_hb[(size_t)NPTS * CCH];        // h in fp16, 128 MB
__device__ float g_colsum[CCH];
__device__ float g_colsq[CCH];
__device__ float g_mu[CCH];
__device__ float g_a[CCH];
__device__ float g_nll;
__device__ float g_vcnt;
__device__ float g_l1;
__device__ float g_cos;
__device__ float g_msum;

// ---------------- PTX helpers (plain-sm_103-safe) ----------------
__device__ __forceinline__ uint32_t smem_u32(const void* p) {
    uint32_t a;
    asm("{ .reg .u64 t; cvta.to.shared.u64 t, %1; cvt.u32.u64 %0, t; }" : "=r"(a) : "l"(p));
    return a;
}
__device__ __forceinline__ void sts64(uint32_t a, uint32_t x, uint32_t y) {
    asm volatile("st.shared.v2.b32 [%0], {%1,%2};" :: "r"(a), "r"(x), "r"(y));
}
__device__ __forceinline__ void cpa16(uint32_t dst, const void* src) {
    asm volatile("cp.async.cg.shared.global [%0], [%1], 16;" :: "r"(dst), "l"(src));
}
__device__ __forceinline__ void cpa_commit() {
    asm volatile("cp.async.commit_group;" ::: "memory");
}
__device__ __forceinline__ void ldm4(uint32_t* r, uint32_t a) {
    asm volatile("ldmatrix.sync.aligned.m8n8.x4.shared.b16 {%0,%1,%2,%3}, [%4];"
                 : "=r"(r[0]), "=r"(r[1]), "=r"(r[2]), "=r"(r[3]) : "r"(a));
}
__device__ __forceinline__ void mma_f16(float& d0, float& d1, float& d2, float& d3,
                                        uint32_t a0, uint32_t a1, uint32_t a2, uint32_t a3,
                                        uint32_t b0, uint32_t b1) {
    asm volatile("mma.sync.aligned.m16n8k16.row.col.f32.f16.f16.f32 "
                 "{%0,%1,%2,%3}, {%4,%5,%6,%7}, {%8,%9}, {%0,%1,%2,%3};"
                 : "+f"(d0), "+f"(d1), "+f"(d2), "+f"(d3)
                 : "r"(a0), "r"(a1), "r"(a2), "r"(a3), "r"(b0), "r"(b1));
}
__device__ __forceinline__ uint32_t pkh(__half a, __half b) {
    __half2 t = __halves2half2(a, b);
    return *(uint32_t*)&t;
}

// SMEM stage layout (bytes). Row stride 80 B -> conflict-free ldmatrix.
#define A_OFF 0               // 128 rows * 80 = 10240
#define B_OFF 10240           // 96 rows * 80 = 7680
#define STG   17920
#define NSTAGE 4
#define DYN_SMEM (NSTAGE * STG)   // 71680

// epilogue layout in dynamic smem (floats): b1[256], bs[32], scs[256], scq[256], nv[2]@800, lg@832 (128*33)
#define EP_B1  0
#define EP_BS  256
#define EP_SCS 288
#define EP_SCQ 544
#define EP_NV  800
#define EP_LG  832

// ---------------- kernel: zero accumulators (idempotent) ----------------
__global__ void zero_kernel() {
    int t = threadIdx.x;
    g_colsum[t] = 0.f;
    g_colsq[t]  = 0.f;
    if (t == 0) {
        g_nll = 0.f; g_vcnt = 0.f; g_l1 = 0.f; g_cos = 0.f; g_msum = 0.f;
    }
}

// ---------------- kernel: build B^T fp16 (w1 + padded ws) ----------------
__global__ void convw_kernel(const float* __restrict__ w1, const float* __restrict__ ws) {
    int n = blockIdx.x;    // 0..287 output channel
    int k = threadIdx.x;   // 0..255 input channel
    float v;
    if (n < 256)             v = w1[(size_t)k * 256 + n];
    else if (n - 256 < KCLS) v = ws[k * KCLS + (n - 256)];
    else                     v = 0.f;
    g_Bh[n * 256 + k] = __float2half_rn(v);
}

// ---------------- GEMM load helpers (K=32 chunks) ----------------
__device__ __forceinline__ void a_issue(const float* __restrict__ feat,
                                        int rowBase, int k0, int tid, float4* va) {
#pragma unroll
    for (int t = 0; t < 4; t++) {
        int i = tid + t * 256;
        int r = i >> 3, s = i & 7;
        va[t] = *(const float4*)(feat + (size_t)(rowBase + r) * 256 + k0 + s * 4);
    }
}
__device__ __forceinline__ void a_store(uint32_t S, int tid, const float4* va) {
#pragma unroll
    for (int t = 0; t < 4; t++) {
        int i = tid + t * 256;
        int r = i >> 3, s = i & 7;
        uint32_t p0 = pkh(__float2half_rn(va[t].x), __float2half_rn(va[t].y));
        uint32_t p1 = pkh(__float2half_rn(va[t].z), __float2half_rn(va[t].w));
        sts64(S + A_OFF + (uint32_t)r * 80 + (uint32_t)s * 8, p0, p1);
    }
}
__device__ __forceinline__ void b_issue(int nbase, int k0h, uint32_t S, int tid) {
    for (int i = tid; i < 384; i += 256) {
        int n = i >> 2, s = i & 3;
        cpa16(S + B_OFF + (uint32_t)n * 80 + (uint32_t)s * 16,
              g_Bh + (size_t)(nbase + n) * 256 + k0h + s * 8);
    }
}

// ---------------- fused GEMM (fp16 HMMA, K=32, 4-stage, 3 CTA/SM) + epilogue ----------------
__global__ __launch_bounds__(256, 3)
void gemm_kernel(const float* __restrict__ feat,
                 const float* __restrict__ b1v,
                 const float* __restrict__ bsv,
                 const int* __restrict__ segment) {
    extern __shared__ char dsm[];

    const int tid = threadIdx.x;
    const int wid = tid >> 5, lane = tid & 31;
    const int nb = blockIdx.x;                 // 0..2 N tile
    const int rowBase = blockIdx.y * 128;
    const int nbase = nb * NB_COLS;
    const int wm = wid & 3, wn = wid >> 2;     // 4m x 2n warps
    const int g = lane >> 2, tg = lane & 3;

    const uint32_t sb = smem_u32(dsm);

    float acc[2][6][4];
#pragma unroll
    for (int f = 0; f < 2; f++)
#pragma unroll
        for (int j = 0; j < 6; j++)
#pragma unroll
            for (int q = 0; q < 4; q++) acc[f][j][q] = 0.f;

    // per-thread ldmatrix base offsets (bytes)
    const uint32_t aOff = A_OFF + (uint32_t)(wm * 32 + (lane & 15)) * 80
                        + (uint32_t)(lane >> 4) * 16;
    const uint32_t bOff = B_OFF
        + (uint32_t)(wn * 48 + (lane & 7) + 8 * (lane >> 4)) * 80
        + (uint32_t)((lane >> 3) & 1) * 16;

    // ---- prologue: fill 3 stages ----
    float4 regA[4];
    a_issue(feat, rowBase, 0, tid, regA);
    b_issue(nbase, 0, sb + 0 * STG, tid);  cpa_commit();
    a_store(sb + 0 * STG, tid, regA);
    a_issue(feat, rowBase, 32, tid, regA);
    b_issue(nbase, 32, sb + 1 * STG, tid); cpa_commit();
    a_store(sb + 1 * STG, tid, regA);
    a_issue(feat, rowBase, 64, tid, regA);
    b_issue(nbase, 64, sb + 2 * STG, tid); cpa_commit();

#pragma unroll 1
    for (int c = 0; c < 8; c++) {
        if (c < 6)       asm volatile("cp.async.wait_group 2;" ::: "memory");
        else if (c == 6) asm volatile("cp.async.wait_group 1;" ::: "memory");
        else             asm volatile("cp.async.wait_group 0;" ::: "memory");
        __syncthreads();

        const uint32_t S = sb + (uint32_t)((c & 3) * STG);
#pragma unroll
        for (int ks = 0; ks < 2; ks++) {
            const uint32_t ko = (uint32_t)ks * 32;
            uint32_t a0[4], a1[4];
            ldm4(a0, S + aOff + ko);
            ldm4(a1, S + aOff + 1280 + ko);
#pragma unroll
            for (int j = 0; j < 3; j++) {
                uint32_t b4[4];
                ldm4(b4, S + bOff + (uint32_t)j * 1280 + ko);
                mma_f16(acc[0][2 * j][0], acc[0][2 * j][1], acc[0][2 * j][2], acc[0][2 * j][3],
                        a0[0], a0[1], a0[2], a0[3], b4[0], b4[1]);
                mma_f16(acc[1][2 * j][0], acc[1][2 * j][1], acc[1][2 * j][2], acc[1][2 * j][3],
                        a1[0], a1[1], a1[2], a1[3], b4[0], b4[1]);
                mma_f16(acc[0][2 * j + 1][0], acc[0][2 * j + 1][1], acc[0][2 * j + 1][2], acc[0][2 * j + 1][3],
                        a0[0], a0[1], a0[2], a0[3], b4[2], b4[3]);
                mma_f16(acc[1][2 * j + 1][0], acc[1][2 * j + 1][1], acc[1][2 * j + 1][2], acc[1][2 * j + 1][3],
                        a1[0], a1[1], a1[2], a1[3], b4[2], b4[3]);
            }
        }

        if (c < 6) a_store(sb + (uint32_t)(((c + 2) & 3) * STG), tid, regA);   // chunk c+2
        if (c < 5) {
            a_issue(feat, rowBase, (c + 3) * 32, tid, regA);                    // chunk c+3
            b_issue(nbase, (c + 3) * 32, sb + (uint32_t)(((c + 3) & 3) * STG), tid);
            cpa_commit();
        }
    }

    // ---------------- epilogue (reuse dynamic smem) ----------------
    __syncthreads();
    float* ep = (float*)dsm;
    if (tid < 256) { ep[EP_B1 + tid] = b1v[tid]; ep[EP_SCS + tid] = 0.f; ep[EP_SCQ + tid] = 0.f; }
    if (tid < 32)  ep[EP_BS + tid] = (tid < KCLS) ? bsv[tid] : 0.f;
    if (tid == 0)  { ep[EP_NV] = 0.f; ep[EP_NV + 1] = 0.f; }
    __syncthreads();

    uint32_t* hb32 = (uint32_t*)g_hb;
#pragma unroll
    for (int j = 0; j < 6; j++) {
        int gc = nbase + wn * 48 + j * 8 + tg * 2;
        if (gc < 256) {
            float bb0 = ep[EP_B1 + gc], bb1 = ep[EP_B1 + gc + 1];
            float cs0 = 0.f, cq0 = 0.f, cs1 = 0.f, cq1 = 0.f;
#pragma unroll
            for (int f = 0; f < 2; f++) {
                int r = rowBase + wm * 32 + f * 16 + g;
                float v00 = acc[f][j][0] + bb0;
                float v01 = acc[f][j][1] + bb1;
                float v10 = acc[f][j][2] + bb0;
                float v11 = acc[f][j][3] + bb1;
                hb32[((size_t)r * 256 + gc) >> 1] =
                    pkh(__float2half_rn(v00), __float2half_rn(v01));
                hb32[((size_t)(r + 8) * 256 + gc) >> 1] =
                    pkh(__float2half_rn(v10), __float2half_rn(v11));
                cs0 += v00 + v10;  cq0 += v00 * v00 + v10 * v10;
                cs1 += v01 + v11;  cq1 += v01 * v01 + v11 * v11;
            }
#pragma unroll
            for (int o = 4; o <= 16; o <<= 1) {
                cs0 += __shfl_xor_sync(0xffffffffu, cs0, o);
                cq0 += __shfl_xor_sync(0xffffffffu, cq0, o);
                cs1 += __shfl_xor_sync(0xffffffffu, cs1, o);
                cq1 += __shfl_xor_sync(0xffffffffu, cq1, o);
            }
            if (g == 0) {
                atomicAdd(&ep[EP_SCS + gc], cs0);     atomicAdd(&ep[EP_SCQ + gc], cq0);
                atomicAdd(&ep[EP_SCS + gc + 1], cs1); atomicAdd(&ep[EP_SCQ + gc + 1], cq1);
            }
        } else {
            int lc = gc - 256;
            float bb0 = ep[EP_BS + lc], bb1 = ep[EP_BS + lc + 1];
#pragma unroll
            for (int f = 0; f < 2; f++) {
                int r = wm * 32 + f * 16 + g;
                ep[EP_LG + r * 33 + lc]           = acc[f][j][0] + bb0;
                ep[EP_LG + r * 33 + lc + 1]       = acc[f][j][1] + bb1;
                ep[EP_LG + (r + 8) * 33 + lc]     = acc[f][j][2] + bb0;
                ep[EP_LG + (r + 8) * 33 + lc + 1] = acc[f][j][3] + bb1;
            }
        }
    }
    __syncthreads();

    // semantic CE (nb==2 holds all 20 logit columns)
    if (nb == 2 && tid < 128) {
        int row = tid;
        float m = -1e30f;
        float lg[KCLS];
#pragma unroll
        for (int q = 0; q < KCLS; q++) { lg[q] = ep[EP_LG + row * 33 + q]; m = fmaxf(m, lg[q]); }
        float se = 0.f;
#pragma unroll
        for (int q = 0; q < KCLS; q++) se += expf(lg[q] - m);
        int t = segment[rowBase + row];
        bool valid = (t != -1);
        float picked = ep[EP_LG + row * 33 + (valid ? t : 0)];
        float vf = valid ? 1.f : 0.f;
        float nll = (m + logf(se) - picked) * vf;
#pragma unroll
        for (int o = 16; o > 0; o >>= 1) {
            nll += __shfl_xor_sync(0xffffffffu, nll, o);
            vf  += __shfl_xor_sync(0xffffffffu, vf, o);
        }
        if (lane == 0) { atomicAdd(&ep[EP_NV], nll); atomicAdd(&ep[EP_NV + 1], vf); }
    }
    {
        int lo = nbase;
        int hi = (nbase + NB_COLS < 256) ? nbase + NB_COLS : 256;
        for (int i = lo + tid; i < hi; i += 256) {
            atomicAdd(&g_colsum[i], ep[EP_SCS + i]);
            atomicAdd(&g_colsq[i], ep[EP_SCQ + i]);
        }
    }
    __syncthreads();
    if (nb == 2 && tid == 0) { atomicAdd(&g_nll, ep[EP_NV]); atomicAdd(&g_vcnt, ep[EP_NV + 1]); }
}

// ---------------- BN parameters ----------------
__global__ void bnprep_kernel(const float* __restrict__ gamma) {
    int c = threadIdx.x;
    const float invN = 1.0f / (float)NPTS;
    float mu  = g_colsum[c] * invN;
    float var = g_colsq[c] * invN - mu * mu;
    g_mu[c] = mu;
    g_a[c]  = gamma[c] / sqrtf(var + 1e-3f);
}

// ---------------- BN + ReLU + bias head + L1/cos losses ----------------
__global__ __launch_bounds__(256)
void bias_kernel(const float* __restrict__ coord,
                 const float* __restrict__ centroid,
                 const int* __restrict__ instance,
                 const float* __restrict__ beta,
                 const float* __restrict__ w2,
                 const float* __restrict__ b2) {
    __shared__ float s_mu[CCH], s_a[CCH], s_beta[CCH];
    __shared__ float s_w2[CCH * 3];
    __shared__ float red[8][3];

    const int tid = threadIdx.x;
    s_mu[tid]   = g_mu[tid];
    s_a[tid]    = g_a[tid];
    s_beta[tid] = beta[tid];
    s_w2[tid]       = w2[tid];
    s_w2[256 + tid] = w2[256 + tid];
    s_w2[512 + tid] = w2[512 + tid];
    __syncthreads();

    const int warp = tid >> 5, lane = tid & 31;
    const float b2x = b2[0], b2y = b2[1], b2z = b2[2];

    float l1acc = 0.f, cosacc = 0.f, mcount = 0.f;

    for (int p = 0; p < 8; p++) {
        int n = blockIdx.x * 64 + warp * 8 + p;
        const uint32_t* hr = (const uint32_t*)(g_hb + (size_t)n * CCH);
        float a0 = 0.f, a1 = 0.f, a2 = 0.f;
#pragma unroll
        for (int t = 0; t < 4; t++) {
            int cp = lane + 32 * t;          // fp16 pair index
            int c = 2 * cp;
            uint32_t u = hr[cp];
            __half2 hb = *(__half2*)&u;
            float v0 = __half2float(hb.x);
            float v1 = __half2float(hb.y);
            v0 = fmaxf((v0 - s_mu[c]) * s_a[c] + s_beta[c], 0.f);
            v1 = fmaxf((v1 - s_mu[c + 1]) * s_a[c + 1] + s_beta[c + 1], 0.f);
            a0 += v0 * s_w2[3 * c + 0] + v1 * s_w2[3 * c + 3];
            a1 += v0 * s_w2[3 * c + 1] + v1 * s_w2[3 * c + 4];
            a2 += v0 * s_w2[3 * c + 2] + v1 * s_w2[3 * c + 5];
        }
#pragma unroll
        for (int o = 16; o > 0; o >>= 1) {
            a0 += __shfl_xor_sync(0xffffffffu, a0, o);
            a1 += __shfl_xor_sync(0xffffffffu, a1, o);
            a2 += __shfl_xor_sync(0xffffffffu, a2, o);
        }
        if (lane == 0) {
            float px = a0 + b2x, py = a1 + b2y, pz = a2 + b2z;
            float gx = centroid[3 * n + 0] - coord[3 * n + 0];
            float gy = centroid[3 * n + 1] - coord[3 * n + 1];
            float gz = centroid[3 * n + 2] - coord[3 * n + 2];
            float mask = (instance[n] != -1) ? 1.f : 0.f;
            float l1 = fabsf(px - gx) + fabsf(py - gy) + fabsf(pz - gz);
            float pn = sqrtf(px * px + py * py + pz * pz) + 1e-8f;
            float gn = sqrtf(gx * gx + gy * gy + gz * gz) + 1e-8f;
            float cs = -(px * gx + py * gy + pz * gz) / (pn * gn);
            l1acc  += l1 * mask;
            cosacc += cs * mask;
            mcount += mask;
        }
    }
    if (lane == 0) {
        red[warp][0] = l1acc;
        red[warp][1] = cosacc;
        red[warp][2] = mcount;
    }
    __syncthreads();
    if (tid == 0) {
        float s0 = 0.f, s1 = 0.f, s2 = 0.f;
        for (int w = 0; w < 8; w++) { s0 += red[w][0]; s1 += red[w][1]; s2 += red[w][2]; }
        atomicAdd(&g_l1, s0);
        atomicAdd(&g_cos, s1);
        atomicAdd(&g_msum, s2);
    }
}

// ---------------- finalize ----------------
__global__ void final_kernel(float* __restrict__ out) {
    float seg_loss = g_nll / (g_vcnt + 1e-8f);
    float l1_loss  = g_l1  / (g_msum + 1e-8f);
    float cos_loss = g_cos / (g_msum + 1e-8f);
    out[0] = seg_loss + l1_loss + cos_loss;
    out[1] = seg_loss;
    out[2] = l1_loss;
    out[3] = cos_loss;
}

// ---------------- launcher ----------------
extern "C" void kernel_launch(void* const* d_in, const int* in_sizes, int n_in,
                              void* d_out, int out_size) {
    const float* feat     = (const float*)d_in[0];
    const float* coord    = (const float*)d_in[1];
    const float* centroid = (const float*)d_in[2];
    const int*   segment  = (const int*)d_in[3];
    const int*   instance = (const int*)d_in[4];
    const float* w1       = (const float*)d_in[5];
    const float* b1       = (const float*)d_in[6];
    const float* gamma    = (const float*)d_in[7];
    const float* beta     = (const float*)d_in[8];
    const float* w2       = (const float*)d_in[9];
    const float* b2       = (const float*)d_in[10];
    const float* ws       = (const float*)d_in[11];
    const float* bs       = (const float*)d_in[12];
    float* out = (float*)d_out;

    static int smem_set = 0;
    if (!smem_set) {
        cudaFuncSetAttribute(gemm_kernel, cudaFuncAttributeMaxDynamicSharedMemorySize, DYN_SMEM);
        smem_set = 1;
    }

    // gemm_kernel as the 4th launch: ncu profiles launch #4.
    zero_kernel<<<1, 256>>>();
    convw_kernel<<<BN_TOT, 256>>>(w1, ws);
    zero_kernel<<<1, 256>>>();
    gemm_kernel<<<dim3(3, NPTS / 128), 256, DYN_SMEM>>>(feat, b1, bs, segment);
    bnprep_kernel<<<1, 256>>>(gamma);
    bias_kernel<<<NPTS / 64, 256>>>(coord, centroid, instance, beta, w2, b2);
    final_kernel<<<1, 1>>>(out);
}

// round 12
// speedup vs baseline: 1.0745x; 1.0745x over previous
#include <cuda_runtime.h>
#include <cuda_bf16.h>
#include <cuda_fp16.h>
#include <math.h>
#include <stdint.h>

#define NPTS 262144
#define CCH  256
#define KCLS 20
#define BN_TOT 288            // 256 h cols + 32 padded logit cols
#define NB_COLS 144           // N columns per CTA (2 N-tiles)

// ---------------- device globals ----------------
__device__ __half g_fh[(size_t)NPTS * CCH];        // feat in fp16, 128 MB
__device__ __half g_Bh[BN_TOT * CCH];              // B^T fp16 [n][k]
__device__ __half g_hb[(size_t)NPTS * CCH];        // h in fp16, 128 MB
__device__ float g_colsum[CCH];
__device__ float g_colsq[CCH];
__device__ float g_mu[CCH];
__device__ float g_a[CCH];
__device__ float g_nll;
__device__ float g_vcnt;
__device__ float g_l1;
__device__ float g_cos;
__device__ float g_msum;

// ---------------- PTX helpers (plain-sm_103-safe) ----------------
__device__ __forceinline__ uint32_t smem_u32(const void* p) {
    uint32_t a;
    asm("{ .reg .u64 t; cvta.to.shared.u64 t, %1; cvt.u32.u64 %0, t; }" : "=r"(a) : "l"(p));
    return a;
}
__device__ __forceinline__ void cpa16(uint32_t dst, const void* src) {
    asm volatile("cp.async.cg.shared.global [%0], [%1], 16;" :: "r"(dst), "l"(src));
}
__device__ __forceinline__ void cpa_commit() {
    asm volatile("cp.async.commit_group;" ::: "memory");
}
__device__ __forceinline__ void ldm4(uint32_t* r, uint32_t a) {
    asm volatile("ldmatrix.sync.aligned.m8n8.x4.shared.b16 {%0,%1,%2,%3}, [%4];"
                 : "=r"(r[0]), "=r"(r[1]), "=r"(r[2]), "=r"(r[3]) : "r"(a));
}
__device__ __forceinline__ void ldm2(uint32_t* r, uint32_t a) {
    asm volatile("ldmatrix.sync.aligned.m8n8.x2.shared.b16 {%0,%1}, [%2];"
                 : "=r"(r[0]), "=r"(r[1]) : "r"(a));
}
__device__ __forceinline__ void mma_f16(float& d0, float& d1, float& d2, float& d3,
                                        uint32_t a0, uint32_t a1, uint32_t a2, uint32_t a3,
                                        uint32_t b0, uint32_t b1) {
    asm volatile("mma.sync.aligned.m16n8k16.row.col.f32.f16.f16.f32 "
                 "{%0,%1,%2,%3}, {%4,%5,%6,%7}, {%8,%9}, {%0,%1,%2,%3};"
                 : "+f"(d0), "+f"(d1), "+f"(d2), "+f"(d3)
                 : "r"(a0), "r"(a1), "r"(a2), "r"(a3), "r"(b0), "r"(b1));
}
__device__ __forceinline__ uint32_t pkh(__half a, __half b) {
    __half2 t = __halves2half2(a, b);
    return *(uint32_t*)&t;
}

// SMEM stage layout (bytes). Row stride 144 B (36 words ≡ 4 mod 32 -> conflict-free ldmatrix).
#define RSTRIDE 144
#define A_OFF 0                       // 128 rows * 144 = 18432
#define B_OFF 18432                   // 144 rows * 144 = 20736
#define STAGE 39168
#define NSTAGE 2
#define DYN_SMEM (NSTAGE * STAGE)

// ---------------- kernel: zero accumulators (idempotent) ----------------
__global__ void zero_kernel() {
    int t = threadIdx.x;
    g_colsum[t] = 0.f;
    g_colsq[t]  = 0.f;
    if (t == 0) {
        g_nll = 0.f; g_vcnt = 0.f; g_l1 = 0.f; g_cos = 0.f; g_msum = 0.f;
    }
}

// ---------------- kernel: build B^T fp16 (w1 + padded ws) ----------------
__global__ void convw_kernel(const float* __restrict__ w1, const float* __restrict__ ws) {
    int n = blockIdx.x;    // 0..287 output channel
    int k = threadIdx.x;   // 0..255 input channel
    float v;
    if (n < 256)             v = w1[(size_t)k * 256 + n];
    else if (n - 256 < KCLS) v = ws[k * KCLS + (n - 256)];
    else                     v = 0.f;
    g_Bh[n * 256 + k] = __float2half_rn(v);
}

// ---------------- kernel: convert feat fp32 -> fp16 (streaming) ----------------
__global__ __launch_bounds__(256)
void convfeat_kernel(const float* __restrict__ feat) {
    size_t i = (size_t)blockIdx.x * 256 + threadIdx.x;
    const float4* f4 = (const float4*)feat;
    uint2* h2 = (uint2*)g_fh;
    const size_t stride = (size_t)16384 * 256;
#pragma unroll
    for (int t = 0; t < 4; t++, i += stride) {
        float4 v = f4[i];
        uint2 o;
        o.x = pkh(__float2half_rn(v.x), __float2half_rn(v.y));
        o.y = pkh(__float2half_rn(v.z), __float2half_rn(v.w));
        h2[i] = o;
    }
}

// ---------------- GEMM load (K=64 chunk, all cp.async) ----------------
__device__ __forceinline__ void ab_issue(int rowBase, int nbase, int k0,
                                         uint32_t S, int tid) {
    // A: 128 rows x 64 halves (128 B) -> 1024 cpa16, 4/thread
#pragma unroll
    for (int t = 0; t < 4; t++) {
        int i = tid + t * 256;
        int r = i >> 3, s = i & 7;
        cpa16(S + A_OFF + (uint32_t)r * RSTRIDE + (uint32_t)s * 16,
              g_fh + (size_t)(rowBase + r) * 256 + k0 + s * 8);
    }
    // B: 144 rows x 64 halves -> 1152 cpa16, 4.5/thread
#pragma unroll
    for (int t = 0; t < 5; t++) {
        int i = tid + t * 256;
        if (i < 1152) {
            int n = i >> 3, s = i & 7;
            cpa16(S + B_OFF + (uint32_t)n * RSTRIDE + (uint32_t)s * 16,
                  g_Bh + (size_t)(nbase + n) * 256 + k0 + s * 8);
        }
    }
}

// ---------------- fused GEMM (fp16 HMMA, K=64, 2-stage, 2 CTA/SM) + epilogue ----------------
__global__ __launch_bounds__(256, 2)
void gemm_kernel(const float* __restrict__ b1v,
                 const float* __restrict__ bsv,
                 const int* __restrict__ segment) {
    extern __shared__ char dsm[];
    __shared__ float s_b1[256];
    __shared__ float s_bs[32];
    __shared__ float s_lg[128][33];
    __shared__ float s_scs[256];
    __shared__ float s_scq[256];
    __shared__ float s_nv[2];

    const int tid = threadIdx.x;
    const int wid = tid >> 5, lane = tid & 31;
    const int nb = blockIdx.x;                 // 0..1 N tile
    const int rowBase = blockIdx.y * 128;
    const int nbase = nb * NB_COLS;
    const int wm = wid & 3, wn = wid >> 2;     // 4m x 2n warps
    const int mwb = wm * 32;
    const int g = lane >> 2, tg = lane & 3;

    const uint32_t sb = smem_u32(dsm);

    if (tid < 256) { s_b1[tid] = b1v[tid]; s_scs[tid] = 0.f; s_scq[tid] = 0.f; }
    if (tid < 32)  s_bs[tid] = (tid < KCLS) ? bsv[tid] : 0.f;
    if (tid == 0)  { s_nv[0] = 0.f; s_nv[1] = 0.f; }

    float acc[2][9][4];
#pragma unroll
    for (int f = 0; f < 2; f++)
#pragma unroll
        for (int j = 0; j < 9; j++)
#pragma unroll
            for (int q = 0; q < 4; q++) acc[f][j][q] = 0.f;

    // per-thread ldmatrix base offsets (bytes)
    const uint32_t aOff = A_OFF + (uint32_t)(mwb + (lane & 15)) * RSTRIDE
                        + (uint32_t)(lane >> 4) * 16;
    const uint32_t bOff4 = B_OFF
        + (uint32_t)(wn * 72 + (lane & 7) + 8 * ((lane >> 4) & 1)) * RSTRIDE
        + (uint32_t)((lane >> 3) & 1) * 16;
    const uint32_t bOff2 = B_OFF
        + (uint32_t)(wn * 72 + 64 + (lane & 7)) * RSTRIDE
        + (uint32_t)((lane >> 3) & 1) * 16;

    // ---- prologue: fill both stages ----
    ab_issue(rowBase, nbase, 0, sb, tid);          cpa_commit();
    ab_issue(rowBase, nbase, 64, sb + STAGE, tid); cpa_commit();

#pragma unroll 1
    for (int c = 0; c < 4; c++) {
        if (c < 3) asm volatile("cp.async.wait_group 1;" ::: "memory");
        else       asm volatile("cp.async.wait_group 0;" ::: "memory");
        __syncthreads();                           // chunk c resident

        const uint32_t S = sb + (uint32_t)((c & 1) * STAGE);
#pragma unroll
        for (int ks = 0; ks < 4; ks++) {
            const uint32_t ko = (uint32_t)ks * 32;
            uint32_t a0[4], a1[4];
            ldm4(a0, S + aOff + ko);
            ldm4(a1, S + aOff + 16 * RSTRIDE + ko);
#pragma unroll
            for (int jj = 0; jj < 4; jj++) {
                uint32_t b4[4];
                ldm4(b4, S + bOff4 + (uint32_t)jj * (16 * RSTRIDE) + ko);
                mma_f16(acc[0][2 * jj][0], acc[0][2 * jj][1], acc[0][2 * jj][2], acc[0][2 * jj][3],
                        a0[0], a0[1], a0[2], a0[3], b4[0], b4[1]);
                mma_f16(acc[1][2 * jj][0], acc[1][2 * jj][1], acc[1][2 * jj][2], acc[1][2 * jj][3],
                        a1[0], a1[1], a1[2], a1[3], b4[0], b4[1]);
                mma_f16(acc[0][2 * jj + 1][0], acc[0][2 * jj + 1][1], acc[0][2 * jj + 1][2], acc[0][2 * jj + 1][3],
                        a0[0], a0[1], a0[2], a0[3], b4[2], b4[3]);
                mma_f16(acc[1][2 * jj + 1][0], acc[1][2 * jj + 1][1], acc[1][2 * jj + 1][2], acc[1][2 * jj + 1][3],
                        a1[0], a1[1], a1[2], a1[3], b4[2], b4[3]);
            }
            uint32_t b2r[2];
            ldm2(b2r, S + bOff2 + ko);
            mma_f16(acc[0][8][0], acc[0][8][1], acc[0][8][2], acc[0][8][3],
                    a0[0], a0[1], a0[2], a0[3], b2r[0], b2r[1]);
            mma_f16(acc[1][8][0], acc[1][8][1], acc[1][8][2], acc[1][8][3],
                    a1[0], a1[1], a1[2], a1[3], b2r[0], b2r[1]);
        }

        if (c < 2) {
            __syncthreads();                       // all warps done reading stage (c&1)
            ab_issue(rowBase, nbase, (c + 2) * 64, S, tid);
            cpa_commit();
        }
    }

    // ---------------- epilogue ----------------
    uint32_t* hb32 = (uint32_t*)g_hb;
#pragma unroll
    for (int j = 0; j < 9; j++) {
        int gc = nbase + wn * 72 + j * 8 + tg * 2;
        if (gc < 256) {
            float bb0 = s_b1[gc], bb1 = s_b1[gc + 1];
            float cs0 = 0.f, cq0 = 0.f, cs1 = 0.f, cq1 = 0.f;
#pragma unroll
            for (int f = 0; f < 2; f++) {
                int r = rowBase + mwb + f * 16 + g;
                float v00 = acc[f][j][0] + bb0;
                float v01 = acc[f][j][1] + bb1;
                float v10 = acc[f][j][2] + bb0;
                float v11 = acc[f][j][3] + bb1;
                hb32[((size_t)r * 256 + gc) >> 1] =
                    pkh(__float2half_rn(v00), __float2half_rn(v01));
                hb32[((size_t)(r + 8) * 256 + gc) >> 1] =
                    pkh(__float2half_rn(v10), __float2half_rn(v11));
                cs0 += v00 + v10;  cq0 += v00 * v00 + v10 * v10;
                cs1 += v01 + v11;  cq1 += v01 * v01 + v11 * v11;
            }
#pragma unroll
            for (int o = 4; o <= 16; o <<= 1) {
                cs0 += __shfl_xor_sync(0xffffffffu, cs0, o);
                cq0 += __shfl_xor_sync(0xffffffffu, cq0, o);
                cs1 += __shfl_xor_sync(0xffffffffu, cs1, o);
                cq1 += __shfl_xor_sync(0xffffffffu, cq1, o);
            }
            if (g == 0) {
                atomicAdd(&s_scs[gc], cs0);     atomicAdd(&s_scq[gc], cq0);
                atomicAdd(&s_scs[gc + 1], cs1); atomicAdd(&s_scq[gc + 1], cq1);
            }
        } else {
            int lc = gc - 256;
            float bb0 = s_bs[lc], bb1 = s_bs[lc + 1];
#pragma unroll
            for (int f = 0; f < 2; f++) {
                int r = mwb + f * 16 + g;
                s_lg[r][lc]         = acc[f][j][0] + bb0;
                s_lg[r][lc + 1]     = acc[f][j][1] + bb1;
                s_lg[r + 8][lc]     = acc[f][j][2] + bb0;
                s_lg[r + 8][lc + 1] = acc[f][j][3] + bb1;
            }
        }
    }
    __syncthreads();

    // semantic CE (N-tile 1 holds all 20 logit columns)
    if (nb == 1 && tid < 128) {
        int row = tid;
        float m = -1e30f;
        float lg[KCLS];
#pragma unroll
        for (int q = 0; q < KCLS; q++) { lg[q] = s_lg[row][q]; m = fmaxf(m, lg[q]); }
        float se = 0.f;
#pragma unroll
        for (int q = 0; q < KCLS; q++) se += expf(lg[q] - m);
        int t = segment[rowBase + row];
        bool valid = (t != -1);
        float picked = s_lg[row][valid ? t : 0];
        float vf = valid ? 1.f : 0.f;
        float nll = (m + logf(se) - picked) * vf;
#pragma unroll
        for (int o = 16; o > 0; o >>= 1) {
            nll += __shfl_xor_sync(0xffffffffu, nll, o);
            vf  += __shfl_xor_sync(0xffffffffu, vf, o);
        }
        if (lane == 0) { atomicAdd(&s_nv[0], nll); atomicAdd(&s_nv[1], vf); }
    }
    {
        int lo = nb * NB_COLS;
        int hi = nb ? 256 : NB_COLS;
        for (int i = lo + tid; i < hi; i += 256) {
            atomicAdd(&g_colsum[i], s_scs[i]);
            atomicAdd(&g_colsq[i], s_scq[i]);
        }
    }
    __syncthreads();
    if (nb == 1 && tid == 0) { atomicAdd(&g_nll, s_nv[0]); atomicAdd(&g_vcnt, s_nv[1]); }
}

// ---------------- BN parameters ----------------
__global__ void bnprep_kernel(const float* __restrict__ gamma) {
    int c = threadIdx.x;
    const float invN = 1.0f / (float)NPTS;
    float mu  = g_colsum[c] * invN;
    float var = g_colsq[c] * invN - mu * mu;
    g_mu[c] = mu;
    g_a[c]  = gamma[c] / sqrtf(var + 1e-3f);
}

// ---------------- BN + ReLU + bias head + L1/cos losses ----------------
__global__ __launch_bounds__(256)
void bias_kernel(const float* __restrict__ coord,
                 const float* __restrict__ centroid,
                 const int* __restrict__ instance,
                 const float* __restrict__ beta,
                 const float* __restrict__ w2,
                 const float* __restrict__ b2) {
    __shared__ float s_mu[CCH], s_a[CCH], s_beta[CCH];
    __shared__ float s_w2[CCH * 3];
    __shared__ float red[8][3];

    const int tid = threadIdx.x;
    s_mu[tid]   = g_mu[tid];
    s_a[tid]    = g_a[tid];
    s_beta[tid] = beta[tid];
    s_w2[tid]       = w2[tid];
    s_w2[256 + tid] = w2[256 + tid];
    s_w2[512 + tid] = w2[512 + tid];
    __syncthreads();

    const int warp = tid >> 5, lane = tid & 31;
    const float b2x = b2[0], b2y = b2[1], b2z = b2[2];

    float l1acc = 0.f, cosacc = 0.f, mcount = 0.f;

    for (int p = 0; p < 8; p++) {
        int n = blockIdx.x * 64 + warp * 8 + p;
        const uint32_t* hr = (const uint32_t*)(g_hb + (size_t)n * CCH);
        float a0 = 0.f, a1 = 0.f, a2 = 0.f;
#pragma unroll
        for (int t = 0; t < 4; t++) {
            int cp = lane + 32 * t;          // fp16 pair index
            int c = 2 * cp;
            uint32_t u = hr[cp];
            __half2 hb = *(__half2*)&u;
            float v0 = __half2float(hb.x);
            float v1 = __half2float(hb.y);
            v0 = fmaxf((v0 - s_mu[c]) * s_a[c] + s_beta[c], 0.f);
            v1 = fmaxf((v1 - s_mu[c + 1]) * s_a[c + 1] + s_beta[c + 1], 0.f);
            a0 += v0 * s_w2[3 * c + 0] + v1 * s_w2[3 * c + 3];
            a1 += v0 * s_w2[3 * c + 1] + v1 * s_w2[3 * c + 4];
            a2 += v0 * s_w2[3 * c + 2] + v1 * s_w2[3 * c + 5];
        }
#pragma unroll
        for (int o = 16; o > 0; o >>= 1) {
            a0 += __shfl_xor_sync(0xffffffffu, a0, o);
            a1 += __shfl_xor_sync(0xffffffffu, a1, o);
            a2 += __shfl_xor_sync(0xffffffffu, a2, o);
        }
        if (lane == 0) {
            float px = a0 + b2x, py = a1 + b2y, pz = a2 + b2z;
            float gx = centroid[3 * n + 0] - coord[3 * n + 0];
            float gy = centroid[3 * n + 1] - coord[3 * n + 1];
            float gz = centroid[3 * n + 2] - coord[3 * n + 2];
            float mask = (instance[n] != -1) ? 1.f : 0.f;
            float l1 = fabsf(px - gx) + fabsf(py - gy) + fabsf(pz - gz);
            float pn = sqrtf(px * px + py * py + pz * pz) + 1e-8f;
            float gn = sqrtf(gx * gx + gy * gy + gz * gz) + 1e-8f;
            float cs = -(px * gx + py * gy + pz * gz) / (pn * gn);
            l1acc  += l1 * mask;
            cosacc += cs * mask;
            mcount += mask;
        }
    }
    if (lane == 0) {
        red[warp][0] = l1acc;
        red[warp][1] = cosacc;
        red[warp][2] = mcount;
    }
    __syncthreads();
    if (tid == 0) {
        float s0 = 0.f, s1 = 0.f, s2 = 0.f;
        for (int w = 0; w < 8; w++) { s0 += red[w][0]; s1 += red[w][1]; s2 += red[w][2]; }
        atomicAdd(&g_l1, s0);
        atomicAdd(&g_cos, s1);
        atomicAdd(&g_msum, s2);
    }
}

// ---------------- finalize ----------------
__global__ void final_kernel(float* __restrict__ out) {
    float seg_loss = g_nll / (g_vcnt + 1e-8f);
    float l1_loss  = g_l1  / (g_msum + 1e-8f);
    float cos_loss = g_cos / (g_msum + 1e-8f);
    out[0] = seg_loss + l1_loss + cos_loss;
    out[1] = seg_loss;
    out[2] = l1_loss;
    out[3] = cos_loss;
}

// ---------------- launcher ----------------
extern "C" void kernel_launch(void* const* d_in, const int* in_sizes, int n_in,
                              void* d_out, int out_size) {
    const float* feat     = (const float*)d_in[0];
    const float* coord    = (const float*)d_in[1];
    const float* centroid = (const float*)d_in[2];
    const int*   segment  = (const int*)d_in[3];
    const int*   instance = (const int*)d_in[4];
    const float* w1       = (const float*)d_in[5];
    const float* b1       = (const float*)d_in[6];
    const float* gamma    = (const float*)d_in[7];
    const float* beta     = (const float*)d_in[8];
    const float* w2       = (const float*)d_in[9];
    const float* b2       = (const float*)d_in[10];
    const float* ws       = (const float*)d_in[11];
    const float* bs       = (const float*)d_in[12];
    float* out = (float*)d_out;

    static int smem_set = 0;
    if (!smem_set) {
        cudaFuncSetAttribute(gemm_kernel, cudaFuncAttributeMaxDynamicSharedMemorySize, DYN_SMEM);
        smem_set = 1;
    }

    // gemm_kernel as the 4th launch: ncu profiles launch #4.
    zero_kernel<<<1, 256>>>();
    convw_kernel<<<BN_TOT, 256>>>(w1, ws);
    convfeat_kernel<<<16384, 256>>>(feat);
    gemm_kernel<<<dim3(2, NPTS / 128), 256, DYN_SMEM>>>(b1, bs, segment);
    bnprep_kernel<<<1, 256>>>(gamma);
    bias_kernel<<<NPTS / 64, 256>>>(coord, centroid, instance, beta, w2, b2);
    final_kernel<<<1, 1>>>(out);
}